// round 8
// baseline (speedup 1.0000x reference)
#include <cuda_runtime.h>

// ---------------------------------------------------------------------------
// DILATE loss. B=128, T=256, D=64, gamma=0.01, alpha=0.5, eps=1e-8, BIG=1e10.
// Wavefront kernels: 2 diagonals per barrier, 4-phase register prefetch rings
// for all global streams, AND 2 independent batch elements per CTA (grid 64)
// interleaved in the same phase loop for cross-batch ILP + barrier amortizing.
// ---------------------------------------------------------------------------

#define BATCH 128
#define TLEN  256
#define NDIAG 511            // 2*TLEN - 1
#define PAD   8              // diag padding each side (ring overshoot)
#define NDIAGT (NDIAG + 2 * PAD)
#define BIGV  1e10f
// exp(x/gamma) = exp2(x * KE2);  KE2 = (1/gamma)*log2(e)
#define KE2   144.26950408889634f
// gamma * ln(2)
#define KL    0.006931471805599453f

__device__ float g_D[(size_t)BATCH * NDIAGT * TLEN];
__device__ float g_R[(size_t)BATCH * NDIAGT * TLEN];
__device__ float g_shape[BATCH];
__device__ float g_num[BATCH];
__device__ float g_den[BATCH];

__device__ __forceinline__ size_t DI(int b, int d, int i) {
    return ((size_t)b * NDIAGT + (d + PAD)) * TLEN + i;
}

__device__ __forceinline__ float ex2f_(float x) {
    float y; asm("ex2.approx.ftz.f32 %0, %1;" : "=f"(y) : "f"(x)); return y;
}
__device__ __forceinline__ float lg2f_(float x) {
    float y; asm("lg2.approx.ftz.f32 %0, %1;" : "=f"(y) : "f"(x)); return y;
}
__device__ __forceinline__ float softmin3(float z0, float z1, float z2) {
    float m = fminf(z0, fminf(z1, z2));
    float s = ex2f_((m - z0) * KE2) + ex2f_((m - z1) * KE2)
            + ex2f_((m - z2) * KE2);
    return m - KL * lg2f_(s);
}

// ---------------------------------------------------------------------------
// Kernel 1: pairwise squared distances in diagonal layout (float4 smem).
// ---------------------------------------------------------------------------
__global__ __launch_bounds__(256) void dist_kernel(
    const float* __restrict__ preds, const float* __restrict__ targets)
{
    __shared__ float pool[2 * 64 * 68 + 128];
    float*  ps  = pool;                   // [64][68]
    float*  ts  = pool + 64 * 68;
    float*  pn  = pool + 2 * 64 * 68;     // [64]
    float*  tn  = pn + 64;
    float4* ps4 = (float4*)ps;            // pitch 17
    float4* ts4 = (float4*)ts;

    const int b  = blockIdx.z;
    const int i0 = blockIdx.y * 64;
    const int j0 = blockIdx.x * 64;
    const int tid = threadIdx.x;

    const float4* pb4 = (const float4*)(preds   + (size_t)b * TLEN * 64 + (size_t)i0 * 64);
    const float4* tb4 = (const float4*)(targets + (size_t)b * TLEN * 64 + (size_t)j0 * 64);

#pragma unroll
    for (int q = 0; q < 4; q++) {
        int idx = q * 256 + tid;          // 0..1023 float4s
        int r = idx >> 4, c4 = idx & 15;
        ps4[r * 17 + c4] = pb4[idx];
        ts4[r * 17 + c4] = tb4[idx];
    }
    __syncthreads();

    if (tid < 128) {
        const float* src = (tid < 64) ? ps : ts;
        float* dst = (tid < 64) ? pn : tn;
        int r = tid & 63;
        float s = 0.0f;
#pragma unroll
        for (int k = 0; k < 64; k++) { float v = src[r * 68 + k]; s = fmaf(v, v, s); }
        dst[r] = s;
    }
    __syncthreads();

    const int tx = tid & 15, ty = tid >> 4;
    const int ib = ty * 4, jb = tx * 4;

    float acc[4][4];
#pragma unroll
    for (int r = 0; r < 4; r++)
#pragma unroll
        for (int c = 0; c < 4; c++) acc[r][c] = 0.0f;

#pragma unroll 4
    for (int kq = 0; kq < 16; kq++) {
        float4 pv[4], tv[4];
#pragma unroll
        for (int r = 0; r < 4; r++) pv[r] = ps4[(ib + r) * 17 + kq];
#pragma unroll
        for (int c = 0; c < 4; c++) tv[c] = ts4[(jb + c) * 17 + kq];
#pragma unroll
        for (int r = 0; r < 4; r++)
#pragma unroll
            for (int c = 0; c < 4; c++) {
                acc[r][c] = fmaf(pv[r].x, tv[c].x, acc[r][c]);
                acc[r][c] = fmaf(pv[r].y, tv[c].y, acc[r][c]);
                acc[r][c] = fmaf(pv[r].z, tv[c].z, acc[r][c]);
                acc[r][c] = fmaf(pv[r].w, tv[c].w, acc[r][c]);
            }
    }

    float pnr[4], tnr[4];
#pragma unroll
    for (int r = 0; r < 4; r++) pnr[r] = pn[ib + r];
#pragma unroll
    for (int c = 0; c < 4; c++) tnr[c] = tn[jb + c];

    __syncthreads();

    // Stage tile diagonally: buf[tdd][ii], tdd = local i+j (0..126), pitch 65.
    float* buf = pool;
#pragma unroll
    for (int r = 0; r < 4; r++)
#pragma unroll
        for (int c = 0; c < 4; c++) {
            int ii = ib + r, jj = jb + c;
            float dv = pnr[r] + tnr[c] - 2.0f * acc[r][c];
            buf[(ii + jj) * 65 + ii] = fmaxf(dv, 0.0f);
        }
    __syncthreads();

    for (int base = 0; base < 128; base += 4) {
        int tdd = base + (tid >> 6);
        int ii  = tid & 63;
        if (tdd < 127) {
            int jj = tdd - ii;
            if (jj >= 0 && jj < 64)
                g_D[DI(b, i0 + j0 + tdd, i0 + ii)] = buf[tdd * 65 + ii];
        }
    }
}

// ---------------------------------------------------------------------------
// Kernel 2: soft-DTW forward. 2 diagonals per barrier, 2 batches per CTA.
// ---------------------------------------------------------------------------
__global__ __launch_bounds__(256) void fwd_kernel()
{
    __shared__ float sR[2][4][260];  // per batch: R[dd][k] at [dd&3][k+2]
    const int b0 = blockIdx.x * 2;
    const int i  = threadIdx.x;

    for (int q = i; q < 2 * 4 * 260; q += 256) ((float*)sR)[q] = BIGV;
    __syncthreads();

    const float* Dp[2]; const float* DpH[2]; float* Rp[2];
    float rA[2][4], rB[2][4], rH[2][4];
#pragma unroll
    for (int q = 0; q < 2; q++) {
        const float* Dbase = g_D + ((size_t)(b0 + q) * NDIAGT + PAD) * TLEN;
        Dp[q]  = Dbase + i;
        DpH[q] = Dbase + i - 1;          // halo column (pad rows keep i=0 safe)
        Rp[q]  = g_R + ((size_t)(b0 + q) * NDIAGT + PAD) * TLEN + i;
#pragma unroll
        for (int k = 0; k < 4; k++) {
            rA[q][k] = Dp[q][(2 * k) * TLEN];
            rB[q][k] = Dp[q][(2 * k + 1) * TLEN];
            rH[q][k] = DpH[q][(2 * k) * TLEN];
        }
    }

    float Rres[2];

    auto fstep = [&](int p, int k) {
        const int d = 2 * p;
#pragma unroll
        for (int q = 0; q < 2; q++) {
            float DY = rA[q][k], DZ = rB[q][k], DXv = rH[q][k];
            rA[q][k] = Dp[q][(d + 8) * TLEN];
            rB[q][k] = Dp[q][(d + 9) * TLEN];
            rH[q][k] = DpH[q][(d + 8) * TLEN];

            const float* rm1 = sR[q][(d + 3) & 3];  // diag d-1
            const float* rm2 = sR[q][(d + 2) & 3];  // diag d-2

            // X = R[d][i-1] (halo)
            bool vX = (i >= 1) && (i <= d + 1) && (d - i < 255);
            float x = softmin3(rm2[i], rm1[i], rm1[i + 1]) + DXv;
            if (d == 0) x = DXv;
            if (!vX) x = BIGV;

            // Y = R[d][i]
            bool vY = (i <= d) && (d - i < 256);
            float z1y = rm1[i + 1];
            float y = softmin3(rm2[i + 1], z1y, rm1[i + 2]) + DY;
            if (d == 0 && i == 0) y = DY;
            if (!vY) y = BIGV;

            // Z = R[d+1][i]
            bool vZ = (i <= d + 1) && (d - i < 255);
            float z = softmin3(z1y, x, y) + DZ;
            if (!vZ) z = BIGV;

            Rp[q][(size_t)d * TLEN]       = y;
            Rp[q][(size_t)(d + 1) * TLEN] = z;
            sR[q][d & 3][i + 2]       = y;
            sR[q][(d + 1) & 3][i + 2] = z;
        }
        __syncthreads();
    };

#pragma unroll 1
    for (int g = 0; g < 63; g++) {
#pragma unroll
        for (int k = 0; k < 4; k++) fstep(g * 4 + k, k);
    }
    fstep(252, 0); fstep(253, 1); fstep(254, 2);

    // Epilogue: diag 510 for both batches.
#pragma unroll
    for (int q = 0; q < 2; q++) {
        const int d = 510;
        float DY = rA[q][3];
        const float* rm1 = sR[q][(d + 3) & 3];
        const float* rm2 = sR[q][(d + 2) & 3];
        float y = softmin3(rm2[i + 1], rm1[i + 1], rm1[i + 2]) + DY;
        if (i < 255) y = BIGV;
        Rp[q][(size_t)d * TLEN] = y;
        if (i == 255) g_shape[b0 + q] = y;   // R[255,255]
    }
}

// ---------------------------------------------------------------------------
// Kernel 3: soft-DTW gradient, reverse. 2 diagonals per barrier, 2 batches/CTA.
// Q = (R - D) * KE2.
// ---------------------------------------------------------------------------
__global__ __launch_bounds__(256) void bwd_kernel()
{
    __shared__ float sE[2][4][260];
    __shared__ float sQ[2][4][260];
    __shared__ float red[2][16];

    const int b0 = blockIdx.x * 2;
    const int i  = threadIdx.x;

    for (int q = i; q < 2 * 4 * 260; q += 256) {
        ((float*)sE)[q] = 0.0f;
        ((float*)sQ)[q] = 0.0f;
    }
    __syncthreads();

    const float* Rp[2]; const float* Dp[2]; const float* RpX[2]; const float* DpX[2];
    float rR0[2][4], rD0[2][4], rR1[2][4], rD1[2][4], rRx[2][4], rDx[2][4];
#pragma unroll
    for (int q = 0; q < 2; q++) {
        const float* Rbase = g_R + ((size_t)(b0 + q) * NDIAGT + PAD) * TLEN;
        const float* Dbase = g_D + ((size_t)(b0 + q) * NDIAGT + PAD) * TLEN;
        Rp[q]  = Rbase + i;
        Dp[q]  = Dbase + i;
        RpX[q] = Rbase + i + 1;          // halo column (pad rows keep i=255 safe)
        DpX[q] = Dbase + i + 1;
#pragma unroll
        for (int k = 0; k < 4; k++) {
            rR0[q][k] = Rp[q][(size_t)(510 - 2 * k) * TLEN];
            rD0[q][k] = Dp[q][(size_t)(510 - 2 * k) * TLEN];
            rR1[q][k] = Rp[q][(size_t)(509 - 2 * k) * TLEN];
            rD1[q][k] = Dp[q][(size_t)(509 - 2 * k) * TLEN];
            rRx[q][k] = RpX[q][(size_t)(510 - 2 * k) * TLEN];
            rDx[q][k] = DpX[q][(size_t)(510 - 2 * k) * TLEN];
        }
    }

    float accS[2] = {0.0f, 0.0f}, accW[2] = {0.0f, 0.0f};

    auto bstep = [&](int p, int k) {
        const int d = 510 - 2 * p;
        const int j = d - i;
#pragma unroll
        for (int q = 0; q < 2; q++) {
            float R0 = rR0[q][k], D0 = rD0[q][k], R1 = rR1[q][k], D1 = rD1[q][k];
            float Rx = rRx[q][k], Dx = rDx[q][k];
            rR0[q][k] = Rp[q][(size_t)(d - 8) * TLEN];
            rD0[q][k] = Dp[q][(size_t)(d - 8) * TLEN];
            rR1[q][k] = Rp[q][(size_t)(d - 9) * TLEN];
            rD1[q][k] = Dp[q][(size_t)(d - 9) * TLEN];
            rRx[q][k] = RpX[q][(size_t)(d - 8) * TLEN];
            rDx[q][k] = DpX[q][(size_t)(d - 8) * TLEN];

            const float* eN1 = sE[q][(d + 1) & 3]; const float* qN1 = sQ[q][(d + 1) & 3];
            const float* eN2 = sE[q][(d + 2) & 3]; const float* qN2 = sQ[q][(d + 2) & 3];

            // Y = E[d][i]
            bool vY = (i <= d) && (j < 256);
            float Y = 0.0f;
            if (vY) {
                float tY = R0 * KE2;
                float e = 0.0f;
                if (i < 255) e = fmaf(eN1[i + 1], ex2f_(qN1[i + 1] - tY), e);
                if (j < 255) e = fmaf(eN1[i],     ex2f_(qN1[i]     - tY), e);
                if (i < 255 && j < 255)
                             e = fmaf(eN2[i + 1], ex2f_(qN2[i + 1] - tY), e);
                Y = e;
            }
            if (d == 510) Y = (i == 255) ? 1.0f : 0.0f;

            // X = E[d][i+1] (halo)
            bool vX = (i < 255) && (i + 1 <= d) && (d - i - 1 < 256);
            float X = 0.0f;
            if (vX) {
                float tX = Rx * KE2;
                float e = 0.0f;
                if (i + 1 < 255) e = fmaf(eN1[i + 2], ex2f_(qN1[i + 2] - tX), e);
                if (j - 1 < 255) e = fmaf(eN1[i + 1], ex2f_(qN1[i + 1] - tX), e);
                if (i + 1 < 255 && j - 1 < 255)
                                 e = fmaf(eN2[i + 2], ex2f_(qN2[i + 2] - tX), e);
                X = e;
            }
            if (d == 510) X = (i + 1 == 255) ? 1.0f : 0.0f;

            // Z = E[d-1][i]
            float QY = (R0 - D0) * KE2;
            float QX = (Rx - Dx) * KE2;
            bool vZ = (i <= d - 1) && (d - 1 - i < 256);
            float Z = 0.0f;
            if (vZ) {
                float tZ = R1 * KE2;
                float e = 0.0f;
                if (i < 255)         e = fmaf(X, ex2f_(QX - tZ), e);
                if (d - 1 - i < 255) e = fmaf(Y, ex2f_(QY - tZ), e);
                if (i < 255 && d - 1 - i < 255)
                                     e = fmaf(eN1[i + 1], ex2f_(qN1[i + 1] - tZ), e);
                Z = e;
            }

            if (vY) { accS[q] += Y; float w = (float)(i - j);       accW[q] = fmaf(Y, w * w, accW[q]); }
            if (vZ) { accS[q] += Z; float w = (float)(i - (j - 1)); accW[q] = fmaf(Z, w * w, accW[q]); }

            sE[q][d & 3][i] = Y;       sQ[q][d & 3][i] = QY;
            sE[q][(d - 1) & 3][i] = Z; sQ[q][(d - 1) & 3][i] = (R1 - D1) * KE2;
        }
        __syncthreads();
    };

#pragma unroll 1
    for (int g = 0; g < 63; g++) {
#pragma unroll
        for (int k = 0; k < 4; k++) bstep(g * 4 + k, k);
    }
    bstep(252, 0); bstep(253, 1); bstep(254, 2);

    // Epilogue: diag 0 (cell (0,0); omega weight = 0).
    if (i == 0) {
#pragma unroll
        for (int q = 0; q < 2; q++) {
            float tY = rR0[q][3] * KE2;
            float e = 0.0f;
            e = fmaf(sE[q][1][1], ex2f_(sQ[q][1][1] - tY), e);
            e = fmaf(sE[q][1][0], ex2f_(sQ[q][1][0] - tY), e);
            e = fmaf(sE[q][2][1], ex2f_(sQ[q][2][1] - tY), e);
            accS[q] += e;
        }
    }

    const int w = i >> 5, l = i & 31;
#pragma unroll
    for (int q = 0; q < 2; q++) {
        float s = accS[q];
        float wv = accW[q] * (1.0f / (255.0f * 255.0f));
#pragma unroll
        for (int off = 16; off; off >>= 1) {
            s  += __shfl_down_sync(0xFFFFFFFFu, s, off);
            wv += __shfl_down_sync(0xFFFFFFFFu, wv, off);
        }
        if (l == 0) { red[q][w] = s; red[q][w + 8] = wv; }
    }
    __syncthreads();
    if (i < 2) {
        float s = 0.0f, wv = 0.0f;
#pragma unroll
        for (int t = 0; t < 8; t++) { s += red[i][t]; wv += red[i][t + 8]; }
        g_den[b0 + i] = s;
        g_num[b0 + i] = wv;
    }
}

// ---------------------------------------------------------------------------
// Kernel 4: final scalar.
// ---------------------------------------------------------------------------
__global__ void final_kernel(float* __restrict__ out)
{
    __shared__ float red[4];
    const int t = threadIdx.x;   // 128 threads, one per batch

    float shape = g_shape[t] * (1.0f / 256.0f);
    float den   = g_den[t]   * (1.0f / 256.0f);
    float num   = g_num[t]   * (1.0f / 256.0f);
    float temporal = num / fmaxf(den, 1e-8f);
    float val = 0.5f * shape + 0.5f * temporal;

#pragma unroll
    for (int off = 16; off; off >>= 1)
        val += __shfl_down_sync(0xFFFFFFFFu, val, off);
    if ((t & 31) == 0) red[t >> 5] = val;
    __syncthreads();
    if (t == 0)
        out[0] = (red[0] + red[1] + red[2] + red[3]) * (1.0f / 128.0f);
}

// ---------------------------------------------------------------------------
extern "C" void kernel_launch(void* const* d_in, const int* in_sizes, int n_in,
                              void* d_out, int out_size)
{
    const float* preds   = (const float*)d_in[0];
    const float* targets = (const float*)d_in[1];

    dist_kernel<<<dim3(4, 4, BATCH), 256>>>(preds, targets);
    fwd_kernel<<<BATCH / 2, 256>>>();
    bwd_kernel<<<BATCH / 2, 256>>>();
    final_kernel<<<1, 128>>>((float*)d_out);
}